// round 16
// baseline (speedup 1.0000x reference)
#include <cuda_runtime.h>
#include <math.h>

#define Tt 2
#define Nn 10000
#define Ee 30000
#define LN_EPS 1e-5f
#define VS 68

typedef unsigned long long ull;

// ---------------- scratch ----------------
__device__ float  g_V[(size_t)Nn * 256];   // SoA (gru w-dots)
__device__ float  g_P[(size_t)Nn * 256];
__device__ float4 g_V4[(size_t)Nn * 64];   // AoS (edge gather)
__device__ float4 g_P4[(size_t)Nn * 64];
__device__ float  g_hfused[Nn * 64];
__device__ float  g_agg[Nn * 64];
__device__ float  g_w[Nn * 64];
__device__ float  g_W1T[64 * 128];
__device__ float  g_W2T[64 * 64];
__device__ float4 g_Wzr4[64 * 64];         // [d*64+tn] = (Wx_z, Wx_r, Wh_z, Wh_r)
__device__ float2 g_Wn[64 * 64];           // (Wx_n, Wh_n)
__device__ int    g_idx[Tt * 2 * Ee];

// ---------------- packed f32x2 helpers ----------------
__device__ __forceinline__ ull dup2(float x) {
    ull r; asm("mov.b64 %0, {%1, %1};" : "=l"(r) : "f"(x)); return r;
}
__device__ __forceinline__ ull pk2(float a, float b) {
    ull r; asm("mov.b64 %0, {%1, %2};" : "=l"(r) : "f"(a), "f"(b)); return r;
}
__device__ __forceinline__ void fma2(ull& acc, ull a, ull b) {
    asm("fma.rn.f32x2 %0, %1, %2, %0;" : "+l"(acc) : "l"(a), "l"(b));
}
__device__ __forceinline__ float2 unpk(ull v) {
    float2 r; asm("mov.b64 {%0, %1}, %2;" : "=f"(r.x), "=f"(r.y) : "l"(v)); return r;
}
#define BARG(id) asm volatile("bar.sync %0, 64;" :: "r"(id) : "memory")

// ---------------- prep: idx convert + weights + packed GRU weights + fuse(t=0) ----------------
__global__ void prep_all(const void* __restrict__ ei,
                         const float* __restrict__ W1,
                         const float* __restrict__ W2,
                         const float* __restrict__ Wx,
                         const float* __restrict__ Wh,
                         const float* __restrict__ hseq0) {
    __shared__ int is64s;
    const int* p = (const int*)ei;
    if (threadIdx.x == 0) is64s = 1;
    __syncthreads();
    for (int i = threadIdx.x; i < 500; i += blockDim.x)
        if (p[2 * i + 1] != 0) is64s = 0;
    __syncthreads();
    int is64 = is64s;
    int gid = blockIdx.x * 256 + threadIdx.x;
    if (gid < Tt * 2 * Ee)
        g_idx[gid] = is64 ? (int)((const long long*)ei)[gid] : p[gid];
    if (gid < 64 * 128) { int o = gid >> 7, k = gid & 127; g_W1T[o * 128 + k] = W1[k * 64 + o]; }
    if (gid < 64 * 64)  { int o = gid >> 6, k = gid & 63;  g_W2T[o * 64 + k]  = W2[k * 64 + o]; }
    if (gid < 64 * 64) {
        int d = gid >> 6, tn = gid & 63;
        g_Wzr4[gid] = make_float4(Wx[d * 192 + tn], Wx[d * 192 + 64 + tn],
                                  Wh[d * 192 + tn], Wh[d * 192 + 64 + tn]);
        g_Wn[gid]   = make_float2(Wx[d * 192 + 128 + tn], Wh[d * 192 + 128 + tn]);
    }
    if (gid < Nn * 64) {
        g_hfused[gid] = 2.f * hseq0[gid];
        g_agg[gid] = 0.f;
    }
}

// ---------------- frames: 16 nodes/block (unchanged) ----------------
__global__ void __launch_bounds__(512) frames_kernel(const float* __restrict__ fW,
                                                     const float* __restrict__ fb) {
    extern __shared__ __align__(16) float smem[];
    float* sfW  = smem;
    float* sH   = sfW + 16384;
    float* sV   = sH + 1024;
    float* sP   = sV + 4096;
    float* sdot = sP + 4096;
    float* sT   = sdot + 256;

    int tid = threadIdx.x;
    int nbase = blockIdx.x * 16;

    {
        const float4* s4 = (const float4*)fW;
        float4* d4 = (float4*)sfW;
#pragma unroll
        for (int i = 0; i < 8; i++) d4[tid + i * 512] = s4[tid + i * 512];
        sH[tid] = g_hfused[nbase * 64 + tid];
        sH[tid + 512] = g_hfused[nbase * 64 + tid + 512];
    }
    __syncthreads();

    int cg = tid & 63, np = tid >> 6;
    int c0 = cg * 4, n0 = np * 2;
    float acc0[4] = {0, 0, 0, 0}, acc1[4] = {0, 0, 0, 0};
    const float* h0 = &sH[n0 * 64];
    const float* h1 = &sH[(n0 + 1) * 64];
#pragma unroll 4
    for (int k = 0; k < 64; k += 4) {
        float4 ha = *(const float4*)&h0[k];
        float4 hb = *(const float4*)&h1[k];
        float va[4] = {ha.x, ha.y, ha.z, ha.w};
        float vb[4] = {hb.x, hb.y, hb.z, hb.w};
#pragma unroll
        for (int kk = 0; kk < 4; kk++) {
            float4 w = *(const float4*)&sfW[(k + kk) * 256 + c0];
            acc0[0] += va[kk] * w.x; acc0[1] += va[kk] * w.y;
            acc0[2] += va[kk] * w.z; acc0[3] += va[kk] * w.w;
            acc1[0] += vb[kk] * w.x; acc1[1] += vb[kk] * w.y;
            acc1[2] += vb[kk] * w.z; acc1[3] += vb[kk] * w.w;
        }
    }
    {
        float4 fbv = *(const float4*)&fb[c0];
        acc0[0] += fbv.x; acc0[1] += fbv.y; acc0[2] += fbv.z; acc0[3] += fbv.w;
        acc1[0] += fbv.x; acc1[1] += fbv.y; acc1[2] += fbv.z; acc1[3] += fbv.w;
    }
    float ss0 = acc0[0]*acc0[0]+acc0[1]*acc0[1]+acc0[2]*acc0[2]+acc0[3]*acc0[3];
    float ss1 = acc1[0]*acc1[0]+acc1[1]*acc1[1]+acc1[2]*acc1[2]+acc1[3]*acc1[3];
#pragma unroll
    for (int m = 1; m < 16; m <<= 1) {
        ss0 += __shfl_xor_sync(0xffffffffu, ss0, m);
        ss1 += __shfl_xor_sync(0xffffffffu, ss1, m);
    }
    float rn0 = 1.f / (sqrtf(ss0) + 1e-8f);
    float rn1 = 1.f / (sqrtf(ss1) + 1e-8f);
#pragma unroll
    for (int cc = 0; cc < 4; cc++) {
        sV[n0 * 256 + c0 + cc] = acc0[cc] * rn0;
        sV[(n0 + 1) * 256 + c0 + cc] = acc1[cc] * rn1;
    }
    __syncthreads();

    if (tid < 384) {
        int did = tid >> 2, l = tid & 3;
        int n = did / 6, p = did - n * 6;
        const int pj[6] = {1, 2, 2, 3, 3, 3}, pk[6] = {0, 0, 1, 0, 1, 2};
        const float* vj = &sV[n * 256 + pj[p] * 64];
        const float* vk = &sV[n * 256 + pk[p] * 64];
        float s = 0.f;
#pragma unroll 4
        for (int i = l; i < 64; i += 4) s += vj[i] * vk[i];
        s += __shfl_xor_sync(0xffffffffu, s, 1);
        s += __shfl_xor_sync(0xffffffffu, s, 2);
        if (l == 0) sdot[n * 16 + pj[p] * 4 + pk[p]] = s;
    }
    __syncthreads();

    if (tid < 16) {
        int n = tid;
        float Tl[4][4];
        for (int j = 0; j < 4; j++) {
            for (int i = 0; i < j; i++) {
                float z = 0.f;
                for (int k = i; k < j; k++) z += sdot[n * 16 + j * 4 + k] * Tl[k][i];
                Tl[j][i] = -2.f * z;
            }
            Tl[j][j] = 2.f;
            for (int i = j + 1; i < 4; i++) Tl[j][i] = 0.f;
        }
        for (int k = 0; k < 4; k++)
            for (int a = 0; a < 4; a++) sT[n * 16 + k * 4 + a] = Tl[k][a];
    }
    __syncthreads();

    int a = c0 >> 6;
#pragma unroll
    for (int idx = 0; idx < 2; idx++) {
        int nl = n0 + idx;
        int ng = nbase + nl;
        float pv[4];
#pragma unroll
        for (int cc = 0; cc < 4; cc++) {
            int i = (c0 & 63) + cc;
            float s = 0.f;
#pragma unroll
            for (int k = 0; k < 4; k++) s += sV[nl * 256 + k * 64 + i] * sT[nl * 16 + k * 4 + a];
            pv[cc] = s;
            sP[nl * 256 + c0 + cc] = s;
        }
        *(float4*)&g_P[(size_t)ng * 256 + c0] = make_float4(pv[0], pv[1], pv[2], pv[3]);
        *(float4*)&g_V[(size_t)ng * 256 + c0] = *(float4*)&sV[nl * 256 + c0];
    }
    __syncthreads();

#pragma unroll
    for (int idx = 0; idx < 2; idx++) {
        int nl = n0 + idx;
        int ng = nbase + nl;
        float4 v4 = make_float4(sV[nl * 256 + cg], sV[nl * 256 + 64 + cg],
                                sV[nl * 256 + 128 + cg], sV[nl * 256 + 192 + cg]);
        float4 p4 = make_float4(sP[nl * 256 + cg], sP[nl * 256 + 64 + cg],
                                sP[nl * 256 + 128 + cg], sP[nl * 256 + 192 + cg]);
        g_V4[(size_t)ng * 64 + cg] = v4;
        g_P4[(size_t)ng * 64 + cg] = p4;
    }
}

// ---------------- persistent fused edge kernel (unchanged from R14) ----------------
#define EGRP (Ee / 4)
#define EDGE_BLOCKS 444
#define GRPF 1544
#define EDGE_SMEM ((64 * 132 + 64 * 68 + 4 * GRPF) * 4)
__global__ void __launch_bounds__(256, 3) edge_kernel(int t,
                                                      const float* __restrict__ b1,
                                                      const float* __restrict__ b2,
                                                      float* __restrict__ Qout) {
    extern __shared__ __align__(16) float sm[];
    __shared__ int sRows[4];
    float* sW1T = sm;
    float* sW2T = sm + 64 * 132;
    float* sE   = sW2T + 64 * 68;

    int tid = threadIdx.x;
    for (int i = tid; i < 64 * 128; i += 256) {
        int o = i >> 7, k = i & 127;
        sW1T[o * 132 + k] = g_W1T[i];
    }
    for (int i = tid; i < 64 * 64; i += 256) {
        int o = i >> 6, k = i & 63;
        sW2T[o * 68 + k] = g_W2T[i];
    }

    int g = tid >> 6, et = tid & 63;
    int bid = g + 1;
    float* eb = sE + g * GRPF;
    float4* sPr4 = (float4*)eb;
    float4* sVc4 = (float4*)(eb + 256);
    float* sVr   = eb + 512;
    float* sVc   = eb + 784;
    float* sPc   = eb + 1056;
    float* sHcat = eb + 1328;
    float* sHc   = eb + 1456;
    float* sG    = eb + 1520;
    float* sS    = eb + 1536;

    int oo = tid >> 2, ee = tid & 3;
    const float* w1 = &sW1T[oo * 132];
    const float* w2 = &sW2T[oo * 68];
    float bb1 = b1[oo], bb2 = b2[oo];
    float* hcatE = sE + ee * GRPF + 1328;
    float* m1E   = sE + ee * GRPF + 1456;
    __syncthreads();

    int grp = blockIdx.x;
    float4 vr4, vc4, pc4, pr4;
    float hr, hc;
    int row, col, nrow, ncol;
    {
        int e = grp * 4 + g;
        row = g_idx[t * 2 * Ee + e];
        col = g_idx[t * 2 * Ee + Ee + e];
        vr4 = g_V4[(size_t)row * 64 + et];
        vc4 = g_V4[(size_t)col * 64 + et];
        pc4 = g_P4[(size_t)col * 64 + et];
        pr4 = g_P4[(size_t)row * 64 + et];
        hr = g_hfused[(size_t)row * 64 + et];
        hc = g_hfused[(size_t)col * 64 + et];
        int ngrp = grp + EDGE_BLOCKS;
        if (ngrp < EGRP) {
            int ne = ngrp * 4 + g;
            nrow = g_idx[t * 2 * Ee + ne];
            ncol = g_idx[t * 2 * Ee + Ee + ne];
        } else { nrow = 0; ncol = 0; }
    }

    for (; grp < EGRP; grp += EDGE_BLOCKS) {
        int e = grp * 4 + g;
        if (et == 0) sRows[g] = row;
        sVr[0 * VS + et] = vr4.x; sVr[1 * VS + et] = vr4.y;
        sVr[2 * VS + et] = vr4.z; sVr[3 * VS + et] = vr4.w;
        sVc[0 * VS + et] = vc4.x; sVc[1 * VS + et] = vc4.y;
        sVc[2 * VS + et] = vc4.z; sVc[3 * VS + et] = vc4.w;
        sPc[0 * VS + et] = pc4.x; sPc[1 * VS + et] = pc4.y;
        sPc[2 * VS + et] = pc4.z; sPc[3 * VS + et] = pc4.w;
        sPr4[et] = pr4;
        sVc4[et] = vc4;
        sHc[et] = hc;
        sHcat[et] = hr;
        int ngrp = grp + EDGE_BLOCKS;
        if (ngrp < EGRP) {
            row = nrow; col = ncol;
            vr4 = g_V4[(size_t)row * 64 + et];
            vc4 = g_V4[(size_t)col * 64 + et];
            pc4 = g_P4[(size_t)col * 64 + et];
            pr4 = g_P4[(size_t)row * 64 + et];
            hr = g_hfused[(size_t)row * 64 + et];
            hc = g_hfused[(size_t)col * 64 + et];
            int n2grp = ngrp + EDGE_BLOCKS;
            if (n2grp < EGRP) {
                int n2e = n2grp * 4 + g;
                nrow = g_idx[t * 2 * Ee + n2e];
                ncol = g_idx[t * 2 * Ee + Ee + n2e];
            }
        }
        BARG(bid);

        {
            int d = et >> 2, l = et & 3;
            const float* va = &sVr[(d >> 2) * VS];
            const float* vb = &sVc[(d & 3) * VS];
            float s = 0.f;
#pragma unroll
            for (int q = 0; q < 16; q++) s += va[l + 4 * q] * vb[l + 4 * q];
            s += __shfl_xor_sync(0xffffffffu, s, 1);
            s += __shfl_xor_sync(0xffffffffu, s, 2);
            if (l == 0) sG[d] = s;
        }
        {
            int d = et >> 3, l = et & 7;
            const float* va = (d < 4) ? &sVr[d * VS] : &sPc[(d - 4) * VS];
            float s = 0.f;
#pragma unroll
            for (int q = 0; q < 8; q++) s += va[l + 8 * q] * sHc[l + 8 * q];
            s += __shfl_xor_sync(0xffffffffu, s, 1);
            s += __shfl_xor_sync(0xffffffffu, s, 2);
            s += __shfl_xor_sync(0xffffffffu, s, 4);
            if (l == 0) sS[d] = s;
        }
        BARG(bid);

        {
            float4 prf = sPr4[et];
            float4 vcf = sVc4[et];
            float prr[4] = {prf.x, prf.y, prf.z, prf.w};
            float vcr[4] = {vcf.x, vcf.y, vcf.z, vcf.w};
            float u[4];
#pragma unroll
            for (int a = 0; a < 4; a++) {
                float s = -sS[a];
#pragma unroll
                for (int b = 0; b < 4; b++) s += sG[a * 4 + b] * sS[4 + b];
                u[a] = s;
            }
            float ht = sHc[et];
#pragma unroll
            for (int a = 0; a < 4; a++) ht += prr[a] * u[a] - vcr[a] * sS[4 + a];
            sHcat[64 + et] = ht;
        }

        {
            int j0 = (et & 15) * 4, ig = et >> 4;
            float4 pc4j[4];
#pragma unroll
            for (int b = 0; b < 4; b++) pc4j[b] = *(const float4*)&sPc[b * VS + j0];
            ull wp[4][2], pcn[4][2];
#pragma unroll
            for (int a = 0; a < 4; a++) {
                float4 vrj = *(const float4*)&sVr[a * VS + j0];
                float g0 = sG[a * 4 + 0], g1 = sG[a * 4 + 1];
                float g2 = sG[a * 4 + 2], g3 = sG[a * 4 + 3];
                float w0 = -vrj.x + g0 * pc4j[0].x + g1 * pc4j[1].x + g2 * pc4j[2].x + g3 * pc4j[3].x;
                float w1v = -vrj.y + g0 * pc4j[0].y + g1 * pc4j[1].y + g2 * pc4j[2].y + g3 * pc4j[3].y;
                float w2v = -vrj.z + g0 * pc4j[0].z + g1 * pc4j[1].z + g2 * pc4j[2].z + g3 * pc4j[3].z;
                float w3 = -vrj.w + g0 * pc4j[0].w + g1 * pc4j[1].w + g2 * pc4j[2].w + g3 * pc4j[3].w;
                wp[a][0] = pk2(w0, w1v);
                wp[a][1] = pk2(w2v, w3);
            }
#pragma unroll
            for (int b = 0; b < 4; b++) {
                pcn[b][0] = pk2(-pc4j[b].x, -pc4j[b].y);
                pcn[b][1] = pk2(-pc4j[b].z, -pc4j[b].w);
            }
            float* qbase = Qout + (size_t)e * 4096;
#pragma unroll 4
            for (int r = 0; r < 16; r++) {
                int i = ig * 16 + r;
                float4 prf = sPr4[i];
                float4 vcf = sVc4[i];
                ull q0 = 0ULL, q1 = 0ULL, d;
                d = dup2(prf.x); fma2(q0, d, wp[0][0]); fma2(q1, d, wp[0][1]);
                d = dup2(prf.y); fma2(q0, d, wp[1][0]); fma2(q1, d, wp[1][1]);
                d = dup2(prf.z); fma2(q0, d, wp[2][0]); fma2(q1, d, wp[2][1]);
                d = dup2(prf.w); fma2(q0, d, wp[3][0]); fma2(q1, d, wp[3][1]);
                d = dup2(vcf.x); fma2(q0, d, pcn[0][0]); fma2(q1, d, pcn[0][1]);
                d = dup2(vcf.y); fma2(q0, d, pcn[1][0]); fma2(q1, d, pcn[1][1]);
                d = dup2(vcf.z); fma2(q0, d, pcn[2][0]); fma2(q1, d, pcn[2][1]);
                d = dup2(vcf.w); fma2(q0, d, pcn[3][0]); fma2(q1, d, pcn[3][1]);
                float2 u0 = unpk(q0), u1 = unpk(q1);
                float q[4] = {u0.x, u0.y, u1.x, u1.y};
                int dj = i - j0;
                if (dj >= 0 && dj < 4) q[dj] += 1.f;
                __stcs((float4*)&qbase[i * 64 + j0], make_float4(q[0], q[1], q[2], q[3]));
            }
        }
        __syncthreads();

        {
            ull a0 = 0ULL, a1 = 0ULL;
#pragma unroll 8
            for (int k = 0; k < 128; k += 4) {
                ulonglong2 h2 = *(const ulonglong2*)&hcatE[k];
                ulonglong2 wv = *(const ulonglong2*)&w1[k];
                fma2(a0, h2.x, wv.x);
                fma2(a1, h2.y, wv.y);
            }
            float2 u0 = unpk(a0), u1 = unpk(a1);
            m1E[oo] = fmaxf(u0.x + u0.y + u1.x + u1.y + bb1, 0.f);
        }
        __syncthreads();
        {
            ull a0 = 0ULL, a1 = 0ULL;
#pragma unroll 8
            for (int k = 0; k < 64; k += 4) {
                ulonglong2 h2 = *(const ulonglong2*)&m1E[k];
                ulonglong2 wv = *(const ulonglong2*)&w2[k];
                fma2(a0, h2.x, wv.x);
                fma2(a1, h2.y, wv.y);
            }
            float2 u0 = unpk(a0), u1 = unpk(a1);
            atomicAdd(&g_agg[(size_t)sRows[ee] * 64 + oo],
                      u0.x + u0.y + u1.x + u1.y + bb2);
        }
        __syncthreads();
    }
}

// ---------------- persistent GRU: 16 nodes/group-iter, 2 nodes/thread ----------------
#define GRU_BLOCKS 296
// smem floats: sWzr4 16384 | sWn 8192 | sah 2048 | so 1024 | red 64 | ssv 64 = 27776
#define GRU_SMEM ((16384 + 8192 + 2048 + 1024 + 64 + 64) * 4)
__global__ void __launch_bounds__(512, 2) gru_kernel(const float* __restrict__ gb,
                                                     const float* __restrict__ gamma,
                                                     const float* __restrict__ beta,
                                                     float* __restrict__ out_h,
                                                     float* __restrict__ out_last,
                                                     const float* __restrict__ hseq_next) {
    extern __shared__ __align__(16) float smem[];
    float4* sWzr4 = (float4*)smem;               // [64 d][64 tn] -> 16384 floats
    float2* sWn   = (float2*)(smem + 16384);     // 8192 floats
    float2* sah   = (float2*)(smem + 24576);     // [16 node][64 d] -> 2048 floats
    float*  so    = smem + 26624;                // [16][64] -> 1024 floats
    float*  red   = smem + 27648;                // [16][4] -> 64 floats
    float*  ssv   = smem + 27712;                // [16][4] -> 64 floats

    int tid = threadIdx.x;
    {
        const float4* a4 = (const float4*)g_Wzr4;
        const float4* c4 = (const float4*)g_Wn;
        float4* d1 = (float4*)sWzr4;
        float4* d3 = (float4*)sWn;
#pragma unroll
        for (int i = 0; i < 8; i++) d1[tid + i * 512] = a4[tid + i * 512];
#pragma unroll
        for (int i = 0; i < 4; i++) d3[tid + i * 512] = c4[tid + i * 512];
    }

    int ln = tid >> 6, tn = tid & 63;
    int bid = ln + 1;
    float gbz = gb[tn], gbr = gb[64 + tn], gbn = gb[128 + tn];
    float gam = gamma[tn], bet = beta[tn];
    __syncthreads();

    for (int nb = blockIdx.x; nb < Nn / 16; nb += GRU_BLOCKS) {
        int nbase = nb * 16;
        int n0 = nbase + ln, n1 = nbase + 8 + ln;
        // stage (agg, hfused) for 16 nodes: 1024 float2, 512 threads -> 2 each
        sah[tid] = make_float2(g_agg[nbase * 64 + tid], g_hfused[nbase * 64 + tid]);
        sah[tid + 512] = make_float2(g_agg[nbase * 64 + tid + 512],
                                     g_hfused[nbase * 64 + tid + 512]);
        __syncthreads();

        const float2* ah0p = &sah[ln * 64];
        const float2* ah1p = &sah[(ln + 8) * 64];
        ull axzr0 = 0ULL, ahzr0 = 0ULL, an20 = 0ULL;
        ull axzr1 = 0ULL, ahzr1 = 0ULL, an21 = 0ULL;
#pragma unroll 8
        for (int d = 0; d < 64; d++) {
            float4 zr = sWzr4[d * 64 + tn];
            float2 wn = sWn[d * 64 + tn];
            ull zrxy = pk2(zr.x, zr.y), zrzw = pk2(zr.z, zr.w), wnp = pk2(wn.x, wn.y);
            float2 ah0 = ah0p[d];
            float2 ah1 = ah1p[d];
            fma2(axzr0, dup2(ah0.x), zrxy);
            fma2(ahzr0, dup2(ah0.y), zrzw);
            fma2(an20, pk2(ah0.x, ah0.y), wnp);
            fma2(axzr1, dup2(ah1.x), zrxy);
            fma2(ahzr1, dup2(ah1.y), zrzw);
            fma2(an21, pk2(ah1.x, ah1.y), wnp);
        }
        float o0, o1;
#pragma unroll
        for (int sel = 0; sel < 2; sel++) {
            float2 xzr = unpk(sel ? axzr1 : axzr0);
            float2 hzr = unpk(sel ? ahzr1 : ahzr0);
            float2 nn2 = unpk(sel ? an21 : an20);
            float hself = (sel ? ah1p : ah0p)[tn].y;
            float z  = 1.f / (1.f + expf(-(xzr.x + hzr.x + gbz)));
            float r  = 1.f / (1.f + expf(-(xzr.y + hzr.y + gbr)));
            float nn = tanhf(nn2.x + r * nn2.y + gbn);
            float hn = (1.f - z) * nn + z * hself;
            // LN: warp-reduce (sum, sumsq)
            float s1 = hn, s2 = hn * hn;
#pragma unroll
            for (int m = 16; m >= 1; m >>= 1) {
                s1 += __shfl_xor_sync(0xffffffffu, s1, m);
                s2 += __shfl_xor_sync(0xffffffffu, s2, m);
            }
            int nodei = ln + sel * 8;
            if ((tn & 31) == 0) {
                red[nodei * 4 + (tn >> 5) * 2]     = s1;
                red[nodei * 4 + (tn >> 5) * 2 + 1] = s2;
            }
            if (sel == 0) o0 = hn; else o1 = hn;   // stash hn temporarily
        }
        BARG(bid);
#pragma unroll
        for (int sel = 0; sel < 2; sel++) {
            int nodei = ln + sel * 8;
            int n = sel ? n1 : n0;
            float hn = sel ? o1 : o0;
            float sum   = red[nodei * 4] + red[nodei * 4 + 2];
            float sumsq = red[nodei * 4 + 1] + red[nodei * 4 + 3];
            float mu  = sum * (1.f / 64.f);
            float var = sumsq * (1.f / 64.f) - mu * mu;
            float o = (hn - mu) * rsqrtf(var + LN_EPS) * gam + bet;
            out_h[(size_t)n * 64 + tn] = o;
            if (out_last) out_last[(size_t)n * 64 + tn] = o;
            if (hseq_next) {
                g_hfused[(size_t)n * 64 + tn] = o + hseq_next[(size_t)n * 64 + tn];
                g_agg[(size_t)n * 64 + tn] = 0.f;
            }
            so[nodei * 64 + tn] = o;
            if (sel == 0) o0 = o; else o1 = o;
        }
        BARG(bid);

        // w-dots: 8 dots (2 nodes x 4 a) x 8 lanes within the 64-thread group
        {
            int dd = tn >> 3, l = tn & 7;
            int sel = dd >> 2, a = dd & 3;
            int nodei = ln + sel * 8;
            int n = nbase + nodei;
            const float* gPn = g_P + (size_t)n * 256 + a * 64;
            const float* son = &so[nodei * 64];
            float s = 0.f;
#pragma unroll
            for (int q = 0; q < 8; q++) s += gPn[l + 8 * q] * son[l + 8 * q];
            s += __shfl_xor_sync(0xffffffffu, s, 1);
            s += __shfl_xor_sync(0xffffffffu, s, 2);
            s += __shfl_xor_sync(0xffffffffu, s, 4);
            if (l == 0) ssv[nodei * 4 + a] = s;
        }
        BARG(bid);
#pragma unroll
        for (int sel = 0; sel < 2; sel++) {
            int nodei = ln + sel * 8;
            int n = nbase + nodei;
            float w = sel ? o1 : o0;
            const float* gV = g_V + (size_t)n * 256;
#pragma unroll
            for (int a = 0; a < 4; a++) w -= gV[a * 64 + tn] * ssv[nodei * 4 + a];
            g_w[(size_t)n * 64 + tn] = w;
        }
        __syncthreads();   // protect sah/so/red/ssv before next iteration
    }
}

// ---------------- dis ----------------
__global__ void __launch_bounds__(256) dis_kernel(int t, float* __restrict__ dout) {
    int grp = threadIdx.x >> 6;
    int tid = threadIdx.x & 63;
    int e = blockIdx.x * 4 + grp;
    __shared__ float red[256];
    float v = 0.f;
    if (e < Ee) {
        int row = g_idx[t * 2 * Ee + e];
        int col = g_idx[t * 2 * Ee + Ee + e];
        float d = g_w[row * 64 + tid] - g_w[col * 64 + tid];
        v = d * d;
    }
    red[threadIdx.x] = v;
    __syncthreads();
    for (int s = 32; s > 0; s >>= 1) {
        if (tid < s) red[threadIdx.x] += red[threadIdx.x + s];
        __syncthreads();
    }
    if (tid == 0 && e < Ee) dout[e] = red[grp * 64];
}

// ---------------- launch ----------------
extern "C" void kernel_launch(void* const* d_in, const int* in_sizes, int n_in,
                              void* d_out, int out_size) {
    const float* hseq = (const float*)d_in[0];
    const void*  ei   = d_in[1];
    const float* fW   = (const float*)d_in[2];
    const float* fb   = (const float*)d_in[3];
    const float* W1   = (const float*)d_in[4];
    const float* b1   = (const float*)d_in[5];
    const float* W2   = (const float*)d_in[6];
    const float* b2   = (const float*)d_in[7];
    const float* Wx   = (const float*)d_in[8];
    const float* Wh   = (const float*)d_in[9];
    const float* gb   = (const float*)d_in[10];
    const float* gamma = (const float*)d_in[11];
    const float* beta  = (const float*)d_in[12];

    float* out = (float*)d_out;
    float* out_hlast = out;
    float* out_allh  = out + (size_t)Nn * 64;
    float* out_alld  = out_allh + (size_t)Tt * Nn * 64;
    float* out_allq  = out_alld + (size_t)Tt * Ee;

    const int frames_smem = (22016 + 4096) * 4;
    cudaFuncSetAttribute(frames_kernel, cudaFuncAttributeMaxDynamicSharedMemorySize, frames_smem);
    cudaFuncSetAttribute(edge_kernel,   cudaFuncAttributeMaxDynamicSharedMemorySize, EDGE_SMEM);
    cudaFuncSetAttribute(gru_kernel,    cudaFuncAttributeMaxDynamicSharedMemorySize, GRU_SMEM);

    prep_all<<<(Nn * 64 + 255) / 256, 256>>>(ei, W1, W2, Wx, Wh, hseq);

    for (int t = 0; t < Tt; t++) {
        frames_kernel<<<Nn / 16, 512, frames_smem>>>(fW, fb);
        edge_kernel<<<EDGE_BLOCKS, 256, EDGE_SMEM>>>(t, b1, b2,
                                                     out_allq + (size_t)t * Ee * 4096);
        gru_kernel<<<GRU_BLOCKS, 512, GRU_SMEM>>>(gb, gamma, beta,
                                                  out_allh + (size_t)t * Nn * 64,
                                                  (t == Tt - 1) ? out_hlast : nullptr,
                                                  (t + 1 < Tt) ? (hseq + (size_t)(t + 1) * Nn * 64) : nullptr);
        dis_kernel<<<(Ee + 3) / 4, 256>>>(t, out_alld + (size_t)t * Ee);
    }
}

// round 17
// speedup vs baseline: 1.5274x; 1.5274x over previous
#include <cuda_runtime.h>
#include <math.h>

#define Tt 2
#define Nn 10000
#define Ee 30000
#define LN_EPS 1e-5f
#define VS 68

typedef unsigned long long ull;

// ---------------- scratch ----------------
__device__ float  g_V[(size_t)Nn * 256];   // SoA (gru w-dots)
__device__ float  g_P[(size_t)Nn * 256];
__device__ float4 g_V4[(size_t)Nn * 64];   // AoS (edge gather)
__device__ float4 g_P4[(size_t)Nn * 64];
__device__ float  g_hfused[Nn * 64];
__device__ float  g_agg[Nn * 64];
__device__ float  g_w[Nn * 64];
__device__ float  g_W1T[64 * 128];
__device__ float  g_W2T[64 * 64];
__device__ float2 g_Wxzr[64 * 64];         // [d*64+tn] = (Wx_z, Wx_r)
__device__ float2 g_Whzr[64 * 64];
__device__ float2 g_Wn[64 * 64];           // (Wx_n, Wh_n)
__device__ int    g_idx[Tt * 2 * Ee];

// ---------------- packed f32x2 helpers ----------------
__device__ __forceinline__ ull dup2(float x) {
    ull r; asm("mov.b64 %0, {%1, %1};" : "=l"(r) : "f"(x)); return r;
}
__device__ __forceinline__ ull pk2(float a, float b) {
    ull r; asm("mov.b64 %0, {%1, %2};" : "=l"(r) : "f"(a), "f"(b)); return r;
}
__device__ __forceinline__ void fma2(ull& acc, ull a, ull b) {
    asm("fma.rn.f32x2 %0, %1, %2, %0;" : "+l"(acc) : "l"(a), "l"(b));
}
__device__ __forceinline__ float2 unpk(ull v) {
    float2 r; asm("mov.b64 {%0, %1}, %2;" : "=f"(r.x), "=f"(r.y) : "l"(v)); return r;
}
#define BARG(id) asm volatile("bar.sync %0, 64;" :: "r"(id) : "memory")

// ---------------- prep: idx convert + weights + packed GRU weights + fuse(t=0) ----------------
__global__ void prep_all(const void* __restrict__ ei,
                         const float* __restrict__ W1,
                         const float* __restrict__ W2,
                         const float* __restrict__ Wx,
                         const float* __restrict__ Wh,
                         const float* __restrict__ hseq0) {
    __shared__ int is64s;
    const int* p = (const int*)ei;
    if (threadIdx.x == 0) is64s = 1;
    __syncthreads();
    for (int i = threadIdx.x; i < 500; i += blockDim.x)
        if (p[2 * i + 1] != 0) is64s = 0;
    __syncthreads();
    int is64 = is64s;
    int gid = blockIdx.x * 256 + threadIdx.x;
    if (gid < Tt * 2 * Ee)
        g_idx[gid] = is64 ? (int)((const long long*)ei)[gid] : p[gid];
    if (gid < 64 * 128) { int o = gid >> 7, k = gid & 127; g_W1T[o * 128 + k] = W1[k * 64 + o]; }
    if (gid < 64 * 64)  { int o = gid >> 6, k = gid & 63;  g_W2T[o * 64 + k]  = W2[k * 64 + o]; }
    if (gid < 64 * 64) {
        int d = gid >> 6, tn = gid & 63;
        g_Wxzr[gid] = make_float2(Wx[d * 192 + tn], Wx[d * 192 + 64 + tn]);
        g_Whzr[gid] = make_float2(Wh[d * 192 + tn], Wh[d * 192 + 64 + tn]);
        g_Wn[gid]   = make_float2(Wx[d * 192 + 128 + tn], Wh[d * 192 + 128 + tn]);
    }
    if (gid < Nn * 64) {
        g_hfused[gid] = 2.f * hseq0[gid];
        g_agg[gid] = 0.f;
    }
}

// ---------------- frames: 16 nodes/block ----------------
__global__ void __launch_bounds__(512) frames_kernel(const float* __restrict__ fW,
                                                     const float* __restrict__ fb) {
    extern __shared__ __align__(16) float smem[];
    float* sfW  = smem;
    float* sH   = sfW + 16384;
    float* sV   = sH + 1024;
    float* sP   = sV + 4096;
    float* sdot = sP + 4096;
    float* sT   = sdot + 256;

    int tid = threadIdx.x;
    int nbase = blockIdx.x * 16;

    {
        const float4* s4 = (const float4*)fW;
        float4* d4 = (float4*)sfW;
#pragma unroll
        for (int i = 0; i < 8; i++) d4[tid + i * 512] = s4[tid + i * 512];
        sH[tid] = g_hfused[nbase * 64 + tid];
        sH[tid + 512] = g_hfused[nbase * 64 + tid + 512];
    }
    __syncthreads();

    int cg = tid & 63, np = tid >> 6;
    int c0 = cg * 4, n0 = np * 2;
    float acc0[4] = {0, 0, 0, 0}, acc1[4] = {0, 0, 0, 0};
    const float* h0 = &sH[n0 * 64];
    const float* h1 = &sH[(n0 + 1) * 64];
#pragma unroll 4
    for (int k = 0; k < 64; k += 4) {
        float4 ha = *(const float4*)&h0[k];
        float4 hb = *(const float4*)&h1[k];
        float va[4] = {ha.x, ha.y, ha.z, ha.w};
        float vb[4] = {hb.x, hb.y, hb.z, hb.w};
#pragma unroll
        for (int kk = 0; kk < 4; kk++) {
            float4 w = *(const float4*)&sfW[(k + kk) * 256 + c0];
            acc0[0] += va[kk] * w.x; acc0[1] += va[kk] * w.y;
            acc0[2] += va[kk] * w.z; acc0[3] += va[kk] * w.w;
            acc1[0] += vb[kk] * w.x; acc1[1] += vb[kk] * w.y;
            acc1[2] += vb[kk] * w.z; acc1[3] += vb[kk] * w.w;
        }
    }
    {
        float4 fbv = *(const float4*)&fb[c0];
        acc0[0] += fbv.x; acc0[1] += fbv.y; acc0[2] += fbv.z; acc0[3] += fbv.w;
        acc1[0] += fbv.x; acc1[1] += fbv.y; acc1[2] += fbv.z; acc1[3] += fbv.w;
    }
    float ss0 = acc0[0]*acc0[0]+acc0[1]*acc0[1]+acc0[2]*acc0[2]+acc0[3]*acc0[3];
    float ss1 = acc1[0]*acc1[0]+acc1[1]*acc1[1]+acc1[2]*acc1[2]+acc1[3]*acc1[3];
#pragma unroll
    for (int m = 1; m < 16; m <<= 1) {
        ss0 += __shfl_xor_sync(0xffffffffu, ss0, m);
        ss1 += __shfl_xor_sync(0xffffffffu, ss1, m);
    }
    float rn0 = 1.f / (sqrtf(ss0) + 1e-8f);
    float rn1 = 1.f / (sqrtf(ss1) + 1e-8f);
#pragma unroll
    for (int cc = 0; cc < 4; cc++) {
        sV[n0 * 256 + c0 + cc] = acc0[cc] * rn0;
        sV[(n0 + 1) * 256 + c0 + cc] = acc1[cc] * rn1;
    }
    __syncthreads();

    if (tid < 384) {
        int did = tid >> 2, l = tid & 3;
        int n = did / 6, p = did - n * 6;
        const int pj[6] = {1, 2, 2, 3, 3, 3}, pk[6] = {0, 0, 1, 0, 1, 2};
        const float* vj = &sV[n * 256 + pj[p] * 64];
        const float* vk = &sV[n * 256 + pk[p] * 64];
        float s = 0.f;
#pragma unroll 4
        for (int i = l; i < 64; i += 4) s += vj[i] * vk[i];
        s += __shfl_xor_sync(0xffffffffu, s, 1);
        s += __shfl_xor_sync(0xffffffffu, s, 2);
        if (l == 0) sdot[n * 16 + pj[p] * 4 + pk[p]] = s;
    }
    __syncthreads();

    if (tid < 16) {
        int n = tid;
        float Tl[4][4];
        for (int j = 0; j < 4; j++) {
            for (int i = 0; i < j; i++) {
                float z = 0.f;
                for (int k = i; k < j; k++) z += sdot[n * 16 + j * 4 + k] * Tl[k][i];
                Tl[j][i] = -2.f * z;
            }
            Tl[j][j] = 2.f;
            for (int i = j + 1; i < 4; i++) Tl[j][i] = 0.f;
        }
        for (int k = 0; k < 4; k++)
            for (int a = 0; a < 4; a++) sT[n * 16 + k * 4 + a] = Tl[k][a];
    }
    __syncthreads();

    int a = c0 >> 6;
#pragma unroll
    for (int idx = 0; idx < 2; idx++) {
        int nl = n0 + idx;
        int ng = nbase + nl;
        float pv[4];
#pragma unroll
        for (int cc = 0; cc < 4; cc++) {
            int i = (c0 & 63) + cc;
            float s = 0.f;
#pragma unroll
            for (int k = 0; k < 4; k++) s += sV[nl * 256 + k * 64 + i] * sT[nl * 16 + k * 4 + a];
            pv[cc] = s;
            sP[nl * 256 + c0 + cc] = s;
        }
        *(float4*)&g_P[(size_t)ng * 256 + c0] = make_float4(pv[0], pv[1], pv[2], pv[3]);
        *(float4*)&g_V[(size_t)ng * 256 + c0] = *(float4*)&sV[nl * 256 + c0];
    }
    __syncthreads();

#pragma unroll
    for (int idx = 0; idx < 2; idx++) {
        int nl = n0 + idx;
        int ng = nbase + nl;
        float4 v4 = make_float4(sV[nl * 256 + cg], sV[nl * 256 + 64 + cg],
                                sV[nl * 256 + 128 + cg], sV[nl * 256 + 192 + cg]);
        float4 p4 = make_float4(sP[nl * 256 + cg], sP[nl * 256 + 64 + cg],
                                sP[nl * 256 + 128 + cg], sP[nl * 256 + 192 + cg]);
        g_V4[(size_t)ng * 64 + cg] = v4;
        g_P4[(size_t)ng * 64 + cg] = p4;
    }
}

// ---------------- persistent fused edge kernel ----------------
#define EGRP (Ee / 4)
#define EDGE_BLOCKS 444
#define GRPF 1544
#define EDGE_SMEM ((64 * 132 + 64 * 68 + 4 * GRPF) * 4)
__global__ void __launch_bounds__(256, 3) edge_kernel(int t,
                                                      const float* __restrict__ b1,
                                                      const float* __restrict__ b2,
                                                      float* __restrict__ Qout) {
    extern __shared__ __align__(16) float sm[];
    __shared__ int sRows[4];
    float* sW1T = sm;
    float* sW2T = sm + 64 * 132;
    float* sE   = sW2T + 64 * 68;

    int tid = threadIdx.x;
    for (int i = tid; i < 64 * 128; i += 256) {
        int o = i >> 7, k = i & 127;
        sW1T[o * 132 + k] = g_W1T[i];
    }
    for (int i = tid; i < 64 * 64; i += 256) {
        int o = i >> 6, k = i & 63;
        sW2T[o * 68 + k] = g_W2T[i];
    }

    int g = tid >> 6, et = tid & 63;
    int bid = g + 1;
    float* eb = sE + g * GRPF;
    float4* sPr4 = (float4*)eb;
    float4* sVc4 = (float4*)(eb + 256);
    float* sVr   = eb + 512;
    float* sVc   = eb + 784;
    float* sPc   = eb + 1056;
    float* sHcat = eb + 1328;
    float* sHc   = eb + 1456;
    float* sG    = eb + 1520;
    float* sS    = eb + 1536;

    int oo = tid >> 2, ee = tid & 3;
    const float* w1 = &sW1T[oo * 132];
    const float* w2 = &sW2T[oo * 68];
    float bb1 = b1[oo], bb2 = b2[oo];
    float* hcatE = sE + ee * GRPF + 1328;
    float* m1E   = sE + ee * GRPF + 1456;
    __syncthreads();

    int grp = blockIdx.x;
    float4 vr4, vc4, pc4, pr4;
    float hr, hc;
    int row, col, nrow, ncol;
    {
        int e = grp * 4 + g;
        row = g_idx[t * 2 * Ee + e];
        col = g_idx[t * 2 * Ee + Ee + e];
        vr4 = g_V4[(size_t)row * 64 + et];
        vc4 = g_V4[(size_t)col * 64 + et];
        pc4 = g_P4[(size_t)col * 64 + et];
        pr4 = g_P4[(size_t)row * 64 + et];
        hr = g_hfused[(size_t)row * 64 + et];
        hc = g_hfused[(size_t)col * 64 + et];
        int ngrp = grp + EDGE_BLOCKS;
        if (ngrp < EGRP) {
            int ne = ngrp * 4 + g;
            nrow = g_idx[t * 2 * Ee + ne];
            ncol = g_idx[t * 2 * Ee + Ee + ne];
        } else { nrow = 0; ncol = 0; }
    }

    for (; grp < EGRP; grp += EDGE_BLOCKS) {
        int e = grp * 4 + g;
        if (et == 0) sRows[g] = row;
        sVr[0 * VS + et] = vr4.x; sVr[1 * VS + et] = vr4.y;
        sVr[2 * VS + et] = vr4.z; sVr[3 * VS + et] = vr4.w;
        sVc[0 * VS + et] = vc4.x; sVc[1 * VS + et] = vc4.y;
        sVc[2 * VS + et] = vc4.z; sVc[3 * VS + et] = vc4.w;
        sPc[0 * VS + et] = pc4.x; sPc[1 * VS + et] = pc4.y;
        sPc[2 * VS + et] = pc4.z; sPc[3 * VS + et] = pc4.w;
        sPr4[et] = pr4;
        sVc4[et] = vc4;
        sHc[et] = hc;
        sHcat[et] = hr;
        int ngrp = grp + EDGE_BLOCKS;
        if (ngrp < EGRP) {
            row = nrow; col = ncol;
            vr4 = g_V4[(size_t)row * 64 + et];
            vc4 = g_V4[(size_t)col * 64 + et];
            pc4 = g_P4[(size_t)col * 64 + et];
            pr4 = g_P4[(size_t)row * 64 + et];
            hr = g_hfused[(size_t)row * 64 + et];
            hc = g_hfused[(size_t)col * 64 + et];
            int n2grp = ngrp + EDGE_BLOCKS;
            if (n2grp < EGRP) {
                int n2e = n2grp * 4 + g;
                nrow = g_idx[t * 2 * Ee + n2e];
                ncol = g_idx[t * 2 * Ee + Ee + n2e];
            }
        }
        BARG(bid);

        {
            int d = et >> 2, l = et & 3;
            const float* va = &sVr[(d >> 2) * VS];
            const float* vb = &sVc[(d & 3) * VS];
            float s = 0.f;
#pragma unroll
            for (int q = 0; q < 16; q++) s += va[l + 4 * q] * vb[l + 4 * q];
            s += __shfl_xor_sync(0xffffffffu, s, 1);
            s += __shfl_xor_sync(0xffffffffu, s, 2);
            if (l == 0) sG[d] = s;
        }
        {
            int d = et >> 3, l = et & 7;
            const float* va = (d < 4) ? &sVr[d * VS] : &sPc[(d - 4) * VS];
            float s = 0.f;
#pragma unroll
            for (int q = 0; q < 8; q++) s += va[l + 8 * q] * sHc[l + 8 * q];
            s += __shfl_xor_sync(0xffffffffu, s, 1);
            s += __shfl_xor_sync(0xffffffffu, s, 2);
            s += __shfl_xor_sync(0xffffffffu, s, 4);
            if (l == 0) sS[d] = s;
        }
        BARG(bid);

        {
            float4 prf = sPr4[et];
            float4 vcf = sVc4[et];
            float prr[4] = {prf.x, prf.y, prf.z, prf.w};
            float vcr[4] = {vcf.x, vcf.y, vcf.z, vcf.w};
            float u[4];
#pragma unroll
            for (int a = 0; a < 4; a++) {
                float s = -sS[a];
#pragma unroll
                for (int b = 0; b < 4; b++) s += sG[a * 4 + b] * sS[4 + b];
                u[a] = s;
            }
            float ht = sHc[et];
#pragma unroll
            for (int a = 0; a < 4; a++) ht += prr[a] * u[a] - vcr[a] * sS[4 + a];
            sHcat[64 + et] = ht;
        }

        {
            int j0 = (et & 15) * 4, ig = et >> 4;
            float4 pc4j[4];
#pragma unroll
            for (int b = 0; b < 4; b++) pc4j[b] = *(const float4*)&sPc[b * VS + j0];
            ull wp[4][2], pcn[4][2];
#pragma unroll
            for (int a = 0; a < 4; a++) {
                float4 vrj = *(const float4*)&sVr[a * VS + j0];
                float g0 = sG[a * 4 + 0], g1 = sG[a * 4 + 1];
                float g2 = sG[a * 4 + 2], g3 = sG[a * 4 + 3];
                float w0 = -vrj.x + g0 * pc4j[0].x + g1 * pc4j[1].x + g2 * pc4j[2].x + g3 * pc4j[3].x;
                float w1v = -vrj.y + g0 * pc4j[0].y + g1 * pc4j[1].y + g2 * pc4j[2].y + g3 * pc4j[3].y;
                float w2v = -vrj.z + g0 * pc4j[0].z + g1 * pc4j[1].z + g2 * pc4j[2].z + g3 * pc4j[3].z;
                float w3 = -vrj.w + g0 * pc4j[0].w + g1 * pc4j[1].w + g2 * pc4j[2].w + g3 * pc4j[3].w;
                wp[a][0] = pk2(w0, w1v);
                wp[a][1] = pk2(w2v, w3);
            }
#pragma unroll
            for (int b = 0; b < 4; b++) {
                pcn[b][0] = pk2(-pc4j[b].x, -pc4j[b].y);
                pcn[b][1] = pk2(-pc4j[b].z, -pc4j[b].w);
            }
            float* qbase = Qout + (size_t)e * 4096;
#pragma unroll 4
            for (int r = 0; r < 16; r++) {
                int i = ig * 16 + r;
                float4 prf = sPr4[i];
                float4 vcf = sVc4[i];
                ull q0 = 0ULL, q1 = 0ULL, d;
                d = dup2(prf.x); fma2(q0, d, wp[0][0]); fma2(q1, d, wp[0][1]);
                d = dup2(prf.y); fma2(q0, d, wp[1][0]); fma2(q1, d, wp[1][1]);
                d = dup2(prf.z); fma2(q0, d, wp[2][0]); fma2(q1, d, wp[2][1]);
                d = dup2(prf.w); fma2(q0, d, wp[3][0]); fma2(q1, d, wp[3][1]);
                d = dup2(vcf.x); fma2(q0, d, pcn[0][0]); fma2(q1, d, pcn[0][1]);
                d = dup2(vcf.y); fma2(q0, d, pcn[1][0]); fma2(q1, d, pcn[1][1]);
                d = dup2(vcf.z); fma2(q0, d, pcn[2][0]); fma2(q1, d, pcn[2][1]);
                d = dup2(vcf.w); fma2(q0, d, pcn[3][0]); fma2(q1, d, pcn[3][1]);
                float2 u0 = unpk(q0), u1 = unpk(q1);
                float q[4] = {u0.x, u0.y, u1.x, u1.y};
                int dj = i - j0;
                if (dj >= 0 && dj < 4) q[dj] += 1.f;
                __stcs((float4*)&qbase[i * 64 + j0], make_float4(q[0], q[1], q[2], q[3]));
            }
        }
        __syncthreads();

        {
            ull a0 = 0ULL, a1 = 0ULL;
#pragma unroll 8
            for (int k = 0; k < 128; k += 4) {
                ulonglong2 h2 = *(const ulonglong2*)&hcatE[k];
                ulonglong2 wv = *(const ulonglong2*)&w1[k];
                fma2(a0, h2.x, wv.x);
                fma2(a1, h2.y, wv.y);
            }
            float2 u0 = unpk(a0), u1 = unpk(a1);
            m1E[oo] = fmaxf(u0.x + u0.y + u1.x + u1.y + bb1, 0.f);
        }
        __syncthreads();
        {
            ull a0 = 0ULL, a1 = 0ULL;
#pragma unroll 8
            for (int k = 0; k < 64; k += 4) {
                ulonglong2 h2 = *(const ulonglong2*)&m1E[k];
                ulonglong2 wv = *(const ulonglong2*)&w2[k];
                fma2(a0, h2.x, wv.x);
                fma2(a1, h2.y, wv.y);
            }
            float2 u0 = unpk(a0), u1 = unpk(a1);
            atomicAdd(&g_agg[(size_t)sRows[ee] * 64 + oo],
                      u0.x + u0.y + u1.x + u1.y + bb2);
        }
        __syncthreads();
    }
}

// ---------------- persistent GRU + LN + w (R14 proven version) ----------------
#define GRU_BLOCKS 296
// smem floats: sWxzr 8192 | sWhzr 8192 | sWn 8192 | sah 1024 | so 512 | red 32 | ssv 32
#define GRU_SMEM ((8192 * 3 + 1024 + 512 + 32 + 32) * 4)
__global__ void __launch_bounds__(512, 2) gru_kernel(const float* __restrict__ gb,
                                                     const float* __restrict__ gamma,
                                                     const float* __restrict__ beta,
                                                     float* __restrict__ out_h,
                                                     float* __restrict__ out_last,
                                                     const float* __restrict__ hseq_next) {
    extern __shared__ __align__(16) float smem[];
    float2* sWxzr = (float2*)smem;               // [64 d][64 tn]
    float2* sWhzr = (float2*)(smem + 8192);
    float2* sWn   = (float2*)(smem + 16384);
    float2* sah   = (float2*)(smem + 24576);     // [8 node][64 d]
    float*  so    = smem + 25600;                // [8][64]
    float*  red   = smem + 26112;                // [8][2 halves][2]
    float*  ssv   = smem + 26144;                // [8][4]

    int tid = threadIdx.x;
    {
        const float4* a4 = (const float4*)g_Wxzr;
        const float4* b4 = (const float4*)g_Whzr;
        const float4* c4 = (const float4*)g_Wn;
        float4* d1 = (float4*)sWxzr;
        float4* d2 = (float4*)sWhzr;
        float4* d3 = (float4*)sWn;
#pragma unroll
        for (int i = 0; i < 4; i++) {
            d1[tid + i * 512] = a4[tid + i * 512];
            d2[tid + i * 512] = b4[tid + i * 512];
            d3[tid + i * 512] = c4[tid + i * 512];
        }
    }

    int ln = tid >> 6, tn = tid & 63;
    int bid = ln + 1;
    float gbz = gb[tn], gbr = gb[64 + tn], gbn = gb[128 + tn];
    float gam = gamma[tn], bet = beta[tn];
    __syncthreads();

    for (int nb = blockIdx.x; nb < Nn / 8; nb += GRU_BLOCKS) {
        int nbase = nb * 8;
        int n = nbase + ln;
        sah[tid] = make_float2(g_agg[nbase * 64 + tid], g_hfused[nbase * 64 + tid]);
        __syncthreads();

        const float2* ahn = &sah[ln * 64];
        ull axzr = 0ULL, ahzr = 0ULL, an2 = 0ULL;
#pragma unroll 8
        for (int d = 0; d < 64; d++) {
            float2 ah = ahn[d];
            fma2(axzr, dup2(ah.x), *(const ull*)&sWxzr[d * 64 + tn]);
            fma2(ahzr, dup2(ah.y), *(const ull*)&sWhzr[d * 64 + tn]);
            fma2(an2, pk2(ah.x, ah.y), *(const ull*)&sWn[d * 64 + tn]);
        }
        float2 xzr = unpk(axzr), hzr = unpk(ahzr), nn2 = unpk(an2);
        float z  = 1.f / (1.f + expf(-(xzr.x + hzr.x + gbz)));
        float r  = 1.f / (1.f + expf(-(xzr.y + hzr.y + gbr)));
        float nn = tanhf(nn2.x + r * nn2.y + gbn);
        float hself = ahn[tn].y;
        float hn = (1.f - z) * nn + z * hself;

        float s1 = hn, s2 = hn * hn;
#pragma unroll
        for (int m = 16; m >= 1; m >>= 1) {
            s1 += __shfl_xor_sync(0xffffffffu, s1, m);
            s2 += __shfl_xor_sync(0xffffffffu, s2, m);
        }
        int half = tn >> 5;
        if ((tn & 31) == 0) {
            red[ln * 4 + half * 2]     = s1;
            red[ln * 4 + half * 2 + 1] = s2;
        }
        BARG(bid);
        float sum   = red[ln * 4] + red[ln * 4 + 2];
        float sumsq = red[ln * 4 + 1] + red[ln * 4 + 3];
        float mu  = sum * (1.f / 64.f);
        float var = sumsq * (1.f / 64.f) - mu * mu;
        float o = (hn - mu) * rsqrtf(var + LN_EPS) * gam + bet;
        out_h[(size_t)n * 64 + tn] = o;
        if (out_last) out_last[(size_t)n * 64 + tn] = o;
        if (hseq_next) {
            g_hfused[(size_t)n * 64 + tn] = o + hseq_next[(size_t)n * 64 + tn];
            g_agg[(size_t)n * 64 + tn] = 0.f;
        }
        so[ln * 64 + tn] = o;
        BARG(bid);

        {
            int dd = tn >> 4, l = tn & 15;
            const float* gPn = g_P + (size_t)n * 256 + dd * 64;
            const float* son = &so[ln * 64];
            float s = 0.f;
#pragma unroll
            for (int q = 0; q < 4; q++) s += gPn[l + 16 * q] * son[l + 16 * q];
            s += __shfl_xor_sync(0xffffffffu, s, 1);
            s += __shfl_xor_sync(0xffffffffu, s, 2);
            s += __shfl_xor_sync(0xffffffffu, s, 4);
            s += __shfl_xor_sync(0xffffffffu, s, 8);
            if (l == 0) ssv[ln * 4 + dd] = s;
        }
        BARG(bid);
        float w = o;
        const float* gV = g_V + (size_t)n * 256;
#pragma unroll
        for (int a = 0; a < 4; a++) w -= gV[a * 64 + tn] * ssv[ln * 4 + a];
        g_w[(size_t)n * 64 + tn] = w;
        __syncthreads();
    }
}

// ---------------- dis ----------------
__global__ void __launch_bounds__(256) dis_kernel(int t, float* __restrict__ dout) {
    int grp = threadIdx.x >> 6;
    int tid = threadIdx.x & 63;
    int e = blockIdx.x * 4 + grp;
    __shared__ float red[256];
    float v = 0.f;
    if (e < Ee) {
        int row = g_idx[t * 2 * Ee + e];
        int col = g_idx[t * 2 * Ee + Ee + e];
        float d = g_w[row * 64 + tid] - g_w[col * 64 + tid];
        v = d * d;
    }
    red[threadIdx.x] = v;
    __syncthreads();
    for (int s = 32; s > 0; s >>= 1) {
        if (tid < s) red[threadIdx.x] += red[threadIdx.x + s];
        __syncthreads();
    }
    if (tid == 0 && e < Ee) dout[e] = red[grp * 64];
}

// ---------------- launch ----------------
extern "C" void kernel_launch(void* const* d_in, const int* in_sizes, int n_in,
                              void* d_out, int out_size) {
    const float* hseq = (const float*)d_in[0];
    const void*  ei   = d_in[1];
    const float* fW   = (const float*)d_in[2];
    const float* fb   = (const float*)d_in[3];
    const float* W1   = (const float*)d_in[4];
    const float* b1   = (const float*)d_in[5];
    const float* W2   = (const float*)d_in[6];
    const float* b2   = (const float*)d_in[7];
    const float* Wx   = (const float*)d_in[8];
    const float* Wh   = (const float*)d_in[9];
    const float* gb   = (const float*)d_in[10];
    const float* gamma = (const float*)d_in[11];
    const float* beta  = (const float*)d_in[12];

    float* out = (float*)d_out;
    float* out_hlast = out;
    float* out_allh  = out + (size_t)Nn * 64;
    float* out_alld  = out_allh + (size_t)Tt * Nn * 64;
    float* out_allq  = out_alld + (size_t)Tt * Ee;

    const int frames_smem = (22016 + 4096) * 4;
    cudaFuncSetAttribute(frames_kernel, cudaFuncAttributeMaxDynamicSharedMemorySize, frames_smem);
    cudaFuncSetAttribute(edge_kernel,   cudaFuncAttributeMaxDynamicSharedMemorySize, EDGE_SMEM);
    cudaFuncSetAttribute(gru_kernel,    cudaFuncAttributeMaxDynamicSharedMemorySize, GRU_SMEM);

    prep_all<<<(Nn * 64 + 255) / 256, 256>>>(ei, W1, W2, Wx, Wh, hseq);

    for (int t = 0; t < Tt; t++) {
        frames_kernel<<<Nn / 16, 512, frames_smem>>>(fW, fb);
        edge_kernel<<<EDGE_BLOCKS, 256, EDGE_SMEM>>>(t, b1, b2,
                                                     out_allq + (size_t)t * Ee * 4096);
        gru_kernel<<<GRU_BLOCKS, 512, GRU_SMEM>>>(gb, gamma, beta,
                                                  out_allh + (size_t)t * Nn * 64,
                                                  (t == Tt - 1) ? out_hlast : nullptr,
                                                  (t + 1 < Tt) ? (hseq + (size_t)(t + 1) * Nn * 64) : nullptr);
        dis_kernel<<<(Ee + 3) / 4, 256>>>(t, out_alld + (size_t)t * Ee);
    }
}